// round 6
// baseline (speedup 1.0000x reference)
#include <cuda_runtime.h>
#include <cuda_fp16.h>
#include <math.h>

#define Bn 128
#define Tn 256
#define Hn 128
#define Cn 10

__device__ __forceinline__ float tanh_fast(float v) {
    float y;
    asm("tanh.approx.f32 %0, %1;" : "=f"(y) : "f"(v));
    return y;
}

// ---------------------------------------------------------------------------
// One fused kernel, 512 threads/CTA, CTA b = batch row b.
// Phase 1 lane layout: l = gate*8 + j'  (j' = l&7, gate = l>>3).
//   Thread owns the FULL k=128 dot for gate row g = gate*128 + 8w + j'
//   (64 half2 weights in registers) -> no k-combine shuffle.
//   Activation dance: one MUFU.TANH gives si/sf/tg/so across gate groups;
//   xor16 forms si*tg, xor8 routes sf<->itg (lanes 0..15 compute c),
//   xor16 broadcasts tanh(c) to lanes 16..31 which produce h.
// One __syncthreads per step.
// ---------------------------------------------------------------------------
__global__ __launch_bounds__(512, 1) void lstm_fused(
    const float* __restrict__ x,
    const float* __restrict__ W_ih,
    const float* __restrict__ W_hh,
    const float* __restrict__ b_ih,
    const float* __restrict__ b_hh,
    const float* __restrict__ w_t,
    const float* __restrict__ fc_W,
    const float* __restrict__ fc_b,
    float* __restrict__ out)
{
    extern __shared__ __align__(16) char smraw[];
    float*  Hf   = (float*)smraw;                    // [256][128] f32 131072 B
    float*  sP   = (float*)(smraw + 131072);         // [256][12]     12288 B
    float*  sA   = (float*)(smraw + 143360);         // [256]
    float*  sS   = (float*)(smraw + 144384);         // [256]
    float*  x_sh = (float*)(smraw + 145408);         // [256]
    __half* h16  = (__half*)(smraw + 146432);        // 2 x [128] fp16

    const int b    = blockIdx.x;
    const int tid  = threadIdx.x;
    const int w    = tid >> 5;          // 0..15
    const int l    = tid & 31;
    const int jp   = l & 7;
    const int gt   = l >> 3;            // gate 0:i 1:f 2:g 3:o
    const int g    = gt * Hn + (w << 3) + jp;   // gate row in W_hh
    const int jown = (w << 3) + jp;             // owned hidden unit

    // ---- full W_hh row -> 64 half2 registers ----
    half2 w2[64];
    {
        const float* wrow = W_hh + g * Hn;
#pragma unroll
        for (int i = 0; i < 64; i++)
            w2[i] = __floats2half2_rn(wrow[2 * i], wrow[2 * i + 1]);
    }
    const float wih_r  = W_ih[g];
    const float bias_r = b_ih[g] + b_hh[g];

    if (tid < Tn) x_sh[tid] = x[b * Tn + tid];
    if (tid < 2 * Hn) h16[tid] = __float2half(0.f);
    __syncthreads();

    // ================= Phase 1: recurrence =================
    float c = 0.f;
#pragma unroll 2
    for (int t = 0; t < Tn; t++) {
        const uint4* hp = (const uint4*)(h16 + (t & 1) * Hn);
        half2 a0 = __float2half2_rn(0.f), a1 = a0, a2 = a0, a3 = a0;
#pragma unroll
        for (int q = 0; q < 4; q++) {
            uint4 hv = hp[q];
            a0 = __hfma2(w2[4 * q + 0], *(const half2*)&hv.x, a0);
            a1 = __hfma2(w2[4 * q + 1], *(const half2*)&hv.y, a1);
            a0 = __hfma2(w2[4 * q + 2], *(const half2*)&hv.z, a0);
            a1 = __hfma2(w2[4 * q + 3], *(const half2*)&hv.w, a1);
        }
#pragma unroll
        for (int q = 4; q < 8; q++) {
            uint4 hv = hp[q];
            a2 = __hfma2(w2[4 * q + 0], *(const half2*)&hv.x, a2);
            a3 = __hfma2(w2[4 * q + 1], *(const half2*)&hv.y, a3);
            a2 = __hfma2(w2[4 * q + 2], *(const half2*)&hv.z, a2);
            a3 = __hfma2(w2[4 * q + 3], *(const half2*)&hv.w, a3);
        }
#pragma unroll
        for (int q = 8; q < 12; q++) {
            uint4 hv = hp[q];
            a0 = __hfma2(w2[4 * q + 0], *(const half2*)&hv.x, a0);
            a1 = __hfma2(w2[4 * q + 1], *(const half2*)&hv.y, a1);
            a0 = __hfma2(w2[4 * q + 2], *(const half2*)&hv.z, a0);
            a1 = __hfma2(w2[4 * q + 3], *(const half2*)&hv.w, a1);
        }
#pragma unroll
        for (int q = 12; q < 16; q++) {
            uint4 hv = hp[q];
            a2 = __hfma2(w2[4 * q + 0], *(const half2*)&hv.x, a2);
            a3 = __hfma2(w2[4 * q + 1], *(const half2*)&hv.y, a3);
            a2 = __hfma2(w2[4 * q + 2], *(const half2*)&hv.z, a2);
            a3 = __hfma2(w2[4 * q + 3], *(const half2*)&hv.w, a3);
        }
        float2 f01 = __half22float2(__hadd2(a0, a1));
        float2 f23 = __half22float2(__hadd2(a2, a3));
        float sum = (f01.x + f01.y) + (f23.x + f23.y)
                  + fmaf(x_sh[t], wih_r, bias_r);

        // one MUFU.TANH -> all four activations across gate groups
        const bool isg = (gt == 2);
        float tv  = tanh_fast(isg ? sum : 0.5f * sum);
        float act = isg ? tv : fmaf(0.5f, tv, 0.5f);   // gt0:si gt1:sf gt2:tg gt3:so

        float p16 = __shfl_xor_sync(0xffffffffu, act, 16); // 0<-tg 1<-so 2<-si 3<-sf
        float qv  = ((gt & 1) == 0) ? act * p16 : act;     // gt0,gt2: itg; gt1: sf; gt3: so
        float q8  = __shfl_xor_sync(0xffffffffu, qv, 8);   // gt0<-sf gt1<-itg gt2<-so gt3<-itg

        float sfv  = (gt & 1) ? qv : q8;
        float itgv = (gt & 1) ? q8 : qv;
        c = fmaf(sfv, c, itgv);                    // real on lanes 0..15
        c = fminf(fmaxf(c, -30.f), 30.f);
        float tc  = tanh_fast(c);
        float t16 = __shfl_xor_sync(0xffffffffu, tc, 16);  // gt2<-gt0, gt3<-gt1
        float so  = (gt == 2) ? q8 : act;
        float h   = so * t16;                      // real on lanes 16..31

        if (gt == 2)      h16[((t + 1) & 1) * Hn + jown] = __float2half_rn(h);
        else if (gt == 3) Hf[t * Hn + jown] = h;
        __syncthreads();
    }

    // ================= Phase 2: a, s, p per t (warp w: rows 16w..16w+15) ====
    for (int i = 0; i < 16; i++) {
        const int t = (w << 4) + i;
        const float* hrow = Hf + t * Hn;
        float h0 = hrow[l], h1 = hrow[l + 32], h2 = hrow[l + 64], h3 = hrow[l + 96];
        float t0 = tanh_fast(h0), t1 = tanh_fast(h1), t2 = tanh_fast(h2), t3 = tanh_fast(h3);

        float v[12];
        v[0] = t0 * w_t[l]       + t1 * w_t[l + 32]  + t2 * w_t[l + 64]  + t3 * w_t[l + 96];
        v[1] = t0 * w_t[128 + l] + t1 * w_t[160 + l] + t2 * w_t[192 + l] + t3 * w_t[224 + l];
#pragma unroll
        for (int cc = 0; cc < Cn; cc++) {
            const float* fw = fc_W + cc * Hn;
            v[2 + cc] = h0 * fw[l] + h1 * fw[l + 32] + h2 * fw[l + 64] + h3 * fw[l + 96];
        }
#pragma unroll
        for (int off = 16; off > 0; off >>= 1)
#pragma unroll
            for (int k = 0; k < 12; k++)
                v[k] += __shfl_xor_sync(0xffffffffu, v[k], off);
        if (l == 0) {
            sA[t] = v[0];
            sS[t] = v[1];
            float* pr = sP + t * 12;
#pragma unroll
            for (int cc = 0; cc < Cn; cc++) pr[cc] = v[2 + cc];
            pr[10] = 0.f; pr[11] = 0.f;
        }
    }
    __syncthreads();

    // ================= Phase 3: attention + output =================
    // thread = (t, part): partial over j-1 ≡ part (mod 2), combine via shfl.
    {
        const int t    = tid >> 1;
        const int part = tid & 1;
        const float at = sA[t];
        float acc[10];
#pragma unroll
        for (int i = 0; i < 10; i++) acc[i] = 0.f;

        const int jmaxW = (w << 4) + 15;           // warp-uniform bound
        for (int jm1 = part; jm1 < jmaxW; jm1 += 2) {
            float wgt = __fdividef(1.f, 1.f + __expf(-(at + sS[jm1])));
            wgt = (jm1 < t) ? wgt : 0.f;
            const float4* q = (const float4*)(sP + jm1 * 12);
            float4 q0 = q[0], q1 = q[1], q2 = q[2];
            acc[0] = fmaf(wgt, q0.x, acc[0]); acc[1] = fmaf(wgt, q0.y, acc[1]);
            acc[2] = fmaf(wgt, q0.z, acc[2]); acc[3] = fmaf(wgt, q0.w, acc[3]);
            acc[4] = fmaf(wgt, q1.x, acc[4]); acc[5] = fmaf(wgt, q1.y, acc[5]);
            acc[6] = fmaf(wgt, q1.z, acc[6]); acc[7] = fmaf(wgt, q1.w, acc[7]);
            acc[8] = fmaf(wgt, q2.x, acc[8]); acc[9] = fmaf(wgt, q2.y, acc[9]);
        }
#pragma unroll
        for (int i = 0; i < 10; i++)
            acc[i] += __shfl_xor_sync(0xffffffffu, acc[i], 1);

        if (part == 0) {
            float* o = out + (b * Tn + t) * Cn;
            const float* pr = sP + t * 12;
#pragma unroll
            for (int i = 0; i < 10; i++)
                o[i] = acc[i] + pr[i] + fc_b[i];
        }
    }
}

// ============================================================================
extern "C" void kernel_launch(void* const* d_in, const int* in_sizes, int n_in,
                              void* d_out, int out_size)
{
    const float* x    = (const float*)d_in[0];
    const float* W_ih = (const float*)d_in[1];
    const float* W_hh = (const float*)d_in[2];
    const float* b_ih = (const float*)d_in[3];
    const float* b_hh = (const float*)d_in[4];
    const float* w_t  = (const float*)d_in[5];
    const float* fc_W = (const float*)d_in[6];
    const float* fc_b = (const float*)d_in[7];
    float* out = (float*)d_out;

    const int smem = 146944;
    // Idempotent; also runs on the pre-capture correctness call.
    cudaFuncSetAttribute(lstm_fused, cudaFuncAttributeMaxDynamicSharedMemorySize, smem);

    lstm_fused<<<Bn, 512, smem>>>(x, W_ih, W_hh, b_ih, b_hh, w_t, fc_W, fc_b, out);
}

// round 7
// speedup vs baseline: 1.0198x; 1.0198x over previous
#include <cuda_runtime.h>
#include <cuda_fp16.h>
#include <math.h>

#define Bn 128
#define Tn 256
#define Hn 128
#define Cn 10

__device__ __forceinline__ float tanh_fast(float v) {
    float y;
    asm("tanh.approx.f32 %0, %1;" : "=f"(y) : "f"(v));
    return y;
}

// ---------------------------------------------------------------------------
// Fused kernel, 1024 threads/CTA, CTA b = batch row b.
// Phase 1 lane layout: l = half*16 + gt*4 + jj. Gate row g = gt*128 + 4w + jj,
// k-slice [64*half, 64*half+64). After xor16 combine both halves hold full
// gate sums (redundant copies). Activation dance (3 shuffles total):
//   xor16 : k-combine
//   xor8  : gt0<-tg / gt2<-si (form itg), gt1<-so / gt3<-sf
//   xor4  : gt1,gt3 <- itg  => both compute c and h locally.
// gt1-half0 stores h (fp16 ping-pong); gt1-half1 stores history row (f32).
// One __syncthreads per step.
// ---------------------------------------------------------------------------
__global__ __launch_bounds__(1024, 1) void lstm_fused(
    const float* __restrict__ x,
    const float* __restrict__ W_ih,
    const float* __restrict__ W_hh,
    const float* __restrict__ b_ih,
    const float* __restrict__ b_hh,
    const float* __restrict__ w_t,
    const float* __restrict__ fc_W,
    const float* __restrict__ fc_b,
    float* __restrict__ out)
{
    extern __shared__ __align__(16) char smraw[];
    float*  Hf   = (float*)smraw;                    // [256][128] f32 131072 B
    float*  sP   = (float*)(smraw + 131072);         // [256][12]     12288 B
    float*  sA   = (float*)(smraw + 143360);         // [256]
    float*  sS   = (float*)(smraw + 144384);         // [256]
    float*  x_sh = (float*)(smraw + 145408);         // [256]
    __half* h16  = (__half*)(smraw + 146432);        // 2 x [128] fp16

    const int b    = blockIdx.x;
    const int tid  = threadIdx.x;
    const int w    = tid >> 5;
    const int l    = tid & 31;
    const int jj   = l & 3;
    const int gt   = (l >> 2) & 3;
    const int g    = gt * Hn + (w << 2) + jj;     // gate row
    const int k0   = (l >> 4) * 64;               // k-slice start
    const int jown = (w << 2) + jj;               // owned hidden unit

    // ---- W_hh k-slice -> 32 half2 registers ----
    half2 w2[32];
    {
        const float* wrow = W_hh + g * Hn + k0;
#pragma unroll
        for (int i = 0; i < 32; i++)
            w2[i] = __floats2half2_rn(wrow[2 * i], wrow[2 * i + 1]);
    }
    const float wih_r  = W_ih[g];
    const float bias_r = b_ih[g] + b_hh[g];

    if (tid < Tn) x_sh[tid] = x[b * Tn + tid];
    if (tid < 2 * Hn) h16[tid] = __float2half(0.f);
    __syncthreads();

    // ================= Phase 1: recurrence =================
    float c = 0.f;
#pragma unroll 2
    for (int t = 0; t < Tn; t++) {
        const uint4* hp = (const uint4*)(h16 + (t & 1) * Hn + k0);
        half2 a0 = __float2half2_rn(0.f), a1 = a0, a2 = a0, a3 = a0;
#pragma unroll
        for (int q = 0; q < 4; q++) {
            uint4 hv = hp[q];
            a0 = __hfma2(w2[4 * q + 0], *(const half2*)&hv.x, a0);
            a1 = __hfma2(w2[4 * q + 1], *(const half2*)&hv.y, a1);
            a2 = __hfma2(w2[4 * q + 2], *(const half2*)&hv.z, a2);
            a3 = __hfma2(w2[4 * q + 3], *(const half2*)&hv.w, a3);
        }
#pragma unroll
        for (int q = 4; q < 8; q++) {
            uint4 hv = hp[q];
            a0 = __hfma2(w2[4 * q + 0], *(const half2*)&hv.x, a0);
            a1 = __hfma2(w2[4 * q + 1], *(const half2*)&hv.y, a1);
            a2 = __hfma2(w2[4 * q + 2], *(const half2*)&hv.z, a2);
            a3 = __hfma2(w2[4 * q + 3], *(const half2*)&hv.w, a3);
        }
        float2 f01 = __half22float2(__hadd2(a0, a1));
        float2 f23 = __half22float2(__hadd2(a2, a3));
        float sum = (f01.x + f01.y) + (f23.x + f23.y);
        if (l < 16) sum += fmaf(x_sh[t], wih_r, bias_r);   // add once per gate
        sum += __shfl_xor_sync(0xffffffffu, sum, 16);      // k-combine (dup halves)

        // one MUFU.TANH -> activation for own gate on every lane
        const bool isg = (gt == 2);
        float tv  = tanh_fast(isg ? sum : 0.5f * sum);
        float act = isg ? tv : fmaf(0.5f, tv, 0.5f);       // gt0:si gt1:sf gt2:tg gt3:so

        float x8 = __shfl_xor_sync(0xffffffffu, act, 8);   // gt0<-tg gt1<-so gt2<-si gt3<-sf
        float v  = ((gt & 1) == 0) ? act * x8 : act;       // even: itg; odd: own sigma
        float x4 = __shfl_xor_sync(0xffffffffu, v, 4);     // gt1<-itg(gt0), gt3<-itg(gt2)

        // gt1: sf=act, so=x8 ; gt3: sf=x8, so=act ; both: itg=x4
        float sfv = (gt == 1) ? act : x8;
        float sov = (gt == 1) ? x8  : act;
        c = fmaf(sfv, c, x4);                              // real on gt1, gt3 lanes
        float h = sov * tanh_fast(c);

        if (gt == 1) {
            if (l < 16) h16[((t + 1) & 1) * Hn + jown] = __float2half_rn(h);
            else        Hf[t * Hn + jown] = h;
        }
        __syncthreads();
    }

    // ================= Phase 2: a, s, p per t (warp w: rows 8w..8w+7) =======
    for (int i = 0; i < 8; i++) {
        const int t = (w << 3) + i;
        const float* hrow = Hf + t * Hn;
        float h0 = hrow[l], h1 = hrow[l + 32], h2 = hrow[l + 64], h3 = hrow[l + 96];
        float t0 = tanh_fast(h0), t1 = tanh_fast(h1), t2 = tanh_fast(h2), t3 = tanh_fast(h3);

        float v[12];
        v[0] = t0 * w_t[l]       + t1 * w_t[l + 32]  + t2 * w_t[l + 64]  + t3 * w_t[l + 96];
        v[1] = t0 * w_t[128 + l] + t1 * w_t[160 + l] + t2 * w_t[192 + l] + t3 * w_t[224 + l];
#pragma unroll
        for (int cc = 0; cc < Cn; cc++) {
            const float* fw = fc_W + cc * Hn;
            v[2 + cc] = h0 * fw[l] + h1 * fw[l + 32] + h2 * fw[l + 64] + h3 * fw[l + 96];
        }
#pragma unroll
        for (int off = 16; off > 0; off >>= 1)
#pragma unroll
            for (int k = 0; k < 12; k++)
                v[k] += __shfl_xor_sync(0xffffffffu, v[k], off);
        if (l == 0) {
            sA[t] = v[0];
            sS[t] = v[1];
            float* pr = sP + t * 12;
#pragma unroll
            for (int cc = 0; cc < Cn; cc++) pr[cc] = v[2 + cc];
            pr[10] = 0.f; pr[11] = 0.f;
        }
    }
    __syncthreads();

    // ================= Phase 3: attention + output =================
    // thread = (t, part): partial over j-1 ≡ part (mod 4), combine via shfl.
    {
        const int t    = tid >> 2;
        const int part = tid & 3;
        const float at = sA[t];
        float acc[10];
#pragma unroll
        for (int i = 0; i < 10; i++) acc[i] = 0.f;

        const int jmaxW = (w << 3) + 7;            // warp-uniform bound (max t in warp)
        for (int jm1 = part; jm1 < jmaxW; jm1 += 4) {
            float wgt = __fdividef(1.f, 1.f + __expf(-(at + sS[jm1])));
            wgt = (jm1 < t) ? wgt : 0.f;
            const float4* q = (const float4*)(sP + jm1 * 12);
            float4 q0 = q[0], q1 = q[1], q2 = q[2];
            acc[0] = fmaf(wgt, q0.x, acc[0]); acc[1] = fmaf(wgt, q0.y, acc[1]);
            acc[2] = fmaf(wgt, q0.z, acc[2]); acc[3] = fmaf(wgt, q0.w, acc[3]);
            acc[4] = fmaf(wgt, q1.x, acc[4]); acc[5] = fmaf(wgt, q1.y, acc[5]);
            acc[6] = fmaf(wgt, q1.z, acc[6]); acc[7] = fmaf(wgt, q1.w, acc[7]);
            acc[8] = fmaf(wgt, q2.x, acc[8]); acc[9] = fmaf(wgt, q2.y, acc[9]);
        }
#pragma unroll
        for (int off = 1; off <= 2; off <<= 1)
#pragma unroll
            for (int i = 0; i < 10; i++)
                acc[i] += __shfl_xor_sync(0xffffffffu, acc[i], off);

        if (part == 0) {
            float* o = out + (b * Tn + t) * Cn;
            const float* pr = sP + t * 12;
#pragma unroll
            for (int i = 0; i < 10; i++)
                o[i] = acc[i] + pr[i] + fc_b[i];
        }
    }
}

// ============================================================================
extern "C" void kernel_launch(void* const* d_in, const int* in_sizes, int n_in,
                              void* d_out, int out_size)
{
    const float* x    = (const float*)d_in[0];
    const float* W_ih = (const float*)d_in[1];
    const float* W_hh = (const float*)d_in[2];
    const float* b_ih = (const float*)d_in[3];
    const float* b_hh = (const float*)d_in[4];
    const float* w_t  = (const float*)d_in[5];
    const float* fc_W = (const float*)d_in[6];
    const float* fc_b = (const float*)d_in[7];
    float* out = (float*)d_out;

    const int smem = 146944;
    // Idempotent; also runs on the pre-capture correctness call.
    cudaFuncSetAttribute(lstm_fused, cudaFuncAttributeMaxDynamicSharedMemorySize, smem);

    lstm_fused<<<Bn, 1024, smem>>>(x, W_ih, W_hh, b_ih, b_hh, w_t, fc_W, fc_b, out);
}